// round 12
// baseline (speedup 1.0000x reference)
#include <cuda_runtime.h>
#include <cuda_fp16.h>
#include <cstdint>

#define M_TOT 8192
#define EMBD  1024
#define TSEQ  2048
#define NB    4
#define NH    16
#define HDI   64

// fp16 scratch
__device__ __half g_xh[M_TOT * EMBD];
__device__ __half g_wq[EMBD * EMBD];
__device__ __half g_wk[EMBD * EMBD];
__device__ __half g_wv[EMBD * EMBD];
__device__ __half g_wo[EMBD * EMBD];
__device__ __half g_qh[M_TOT * EMBD];   // [B,H,T,hd], pre-scaled by 1/8
__device__ __half g_kh[M_TOT * EMBD];   // [B,H,T,hd]
__device__ __half g_vh[M_TOT * EMBD];   // [B,H,T,hd]
__device__ __half g_ah[M_TOT * EMBD];   // [B,T,E]

__device__ __forceinline__ unsigned h2(float a, float b) {
    __half2 h = __floats2half2_rn(a, b);
    return *(unsigned*)&h;
}
__device__ __forceinline__ void mma16(float* d, const unsigned* a, const unsigned* b) {
    asm volatile("mma.sync.aligned.m16n8k16.row.col.f32.f16.f16.f32 "
        "{%0,%1,%2,%3}, {%4,%5,%6,%7}, {%8,%9}, {%0,%1,%2,%3};"
        : "+f"(d[0]), "+f"(d[1]), "+f"(d[2]), "+f"(d[3])
        : "r"(a[0]), "r"(a[1]), "r"(a[2]), "r"(a[3]), "r"(b[0]), "r"(b[1]));
}
__device__ __forceinline__ void cp16(uint32_t dst, const void* src) {
    asm volatile("cp.async.cg.shared.global [%0], [%1], 16;" :: "r"(dst), "l"(src));
}
__device__ __forceinline__ void cpcommit() { asm volatile("cp.async.commit_group;"); }
template<int N> __device__ __forceinline__ void cpwait() {
    asm volatile("cp.async.wait_group %0;" :: "n"(N));
}
__device__ __forceinline__ void ldsm4(unsigned& r0, unsigned& r1, unsigned& r2,
                                      unsigned& r3, uint32_t a) {
    asm volatile("ldmatrix.sync.aligned.m8n8.x4.shared.b16 {%0,%1,%2,%3}, [%4];"
                 : "=r"(r0), "=r"(r1), "=r"(r2), "=r"(r3) : "r"(a));
}
__device__ __forceinline__ void ldsm4t(unsigned& r0, unsigned& r1, unsigned& r2,
                                       unsigned& r3, uint32_t a) {
    asm volatile("ldmatrix.sync.aligned.m8n8.x4.trans.shared.b16 {%0,%1,%2,%3}, [%4];"
                 : "=r"(r0), "=r"(r1), "=r"(r2), "=r"(r3) : "r"(a));
}

// ===========================================================================
// fp32 -> fp16 conversion of inputs
// ===========================================================================
__global__ __launch_bounds__(256) void cvt_all(
    const float* __restrict__ x, const float* __restrict__ wq,
    const float* __restrict__ wk, const float* __restrict__ wv,
    const float* __restrict__ wo)
{
    const float* src; __half* dst; int n;
    switch (blockIdx.y) {
        case 0:  src = x;  dst = g_xh; n = M_TOT * EMBD; break;
        case 1:  src = wq; dst = g_wq; n = EMBD * EMBD;  break;
        case 2:  src = wk; dst = g_wk; n = EMBD * EMBD;  break;
        case 3:  src = wv; dst = g_wv; n = EMBD * EMBD;  break;
        default: src = wo; dst = g_wo; n = EMBD * EMBD;  break;
    }
    int stride = gridDim.x * blockDim.x * 8;
    for (int i = (blockIdx.x * blockDim.x + threadIdx.x) * 8; i < n; i += stride) {
        float4 a = *(const float4*)(src + i);
        float4 b = *(const float4*)(src + i + 4);
        uint4 o;
        o.x = h2(a.x, a.y); o.y = h2(a.z, a.w);
        o.z = h2(b.x, b.y); o.w = h2(b.z, b.w);
        *(uint4*)(dst + i) = o;
    }
}

// ===========================================================================
// fp16 GEMM: 128x128 CTA tile, 128 threads / 4 warps, 64x64 warp tile.
// k-chunk 32, 4-stage cp.async (R6 pipeline). Row stride 20 words.
// Per ks: 4 A-LDSM + 4 B-LDSM -> 32 HMMA  (1:4 ratio).
// ===========================================================================
#define GSTG 5120                    // words per stage
#define GEMM_SMEM (4 * GSTG * 4)     // 81920 B

template<int SCATTER>
__device__ __forceinline__ void gemm_body(
    const __half* __restrict__ A, const __half* __restrict__ Bw,
    const float* __restrict__ bias, void* __restrict__ outv,
    int bx, int by, float oscale)
{
    extern __shared__ unsigned smu[];
    const uint32_t sb = (uint32_t)__cvta_generic_to_shared(smu);

    const int tid  = threadIdx.x;
    const int lane = tid & 31, wid = tid >> 5;        // 4 warps
    const int g = lane >> 2, t = lane & 3;
    const int wm = (wid & 1) * 64, wn = (wid >> 1) * 64;
    const int m0 = bx * 128, n0 = by * 128;

    // cp.async: thread tid stages full row tid (32 halves = 64B) of A and B
    const __half* gA = A  + (size_t)(m0 + tid) * EMBD;
    const __half* gB = Bw + (size_t)(n0 + tid) * EMBD;
    const uint32_t dA = sb + tid * 20 * 4;
    const uint32_t dB = dA + 2560 * 4;

    auto issue = [&](int c) {
        if (c < 32) {
            uint32_t so = (uint32_t)(c & 3) * (GSTG * 4);
            const __half* sa = gA + c * 32;
            const __half* sbp = gB + c * 32;
            cp16(dA + so, sa);            cp16(dA + so + 16, sa + 8);
            cp16(dA + so + 32, sa + 16);  cp16(dA + so + 48, sa + 24);
            cp16(dB + so, sbp);           cp16(dB + so + 16, sbp + 8);
            cp16(dB + so + 32, sbp + 16); cp16(dB + so + 48, sbp + 24);
        }
        cpcommit();
    };
    issue(0); issue(1); issue(2);

    const uint32_t aAddr = sb +
        ((wm + (lane & 15)) * 20 + ((lane & 16) ? 4 : 0)) * 4;
    const uint32_t bAddr = sb + 2560 * 4 +
        ((wn + (lane & 7) + ((lane & 16) ? 8 : 0)) * 20 + ((lane & 8) ? 4 : 0)) * 4;

    float acc[4][8][4];
#pragma unroll
    for (int mt = 0; mt < 4; mt++)
#pragma unroll
        for (int nt = 0; nt < 8; nt++)
#pragma unroll
            for (int f = 0; f < 4; f++) acc[mt][nt][f] = 0.f;

    for (int c = 0; c < 32; c++) {
        cpwait<2>();
        __syncthreads();
        issue(c + 3);
        const uint32_t so = (uint32_t)(c & 3) * (GSTG * 4);
#pragma unroll
        for (int ks = 0; ks < 2; ks++) {
            unsigned af[4][4], bf[4][4];
#pragma unroll
            for (int mt = 0; mt < 4; mt++)
                ldsm4(af[mt][0], af[mt][1], af[mt][2], af[mt][3],
                      aAddr + so + mt * (16 * 80) + ks * 32);
#pragma unroll
            for (int np = 0; np < 4; np++)
                ldsm4(bf[np][0], bf[np][1], bf[np][2], bf[np][3],
                      bAddr + so + np * (16 * 80) + ks * 32);
#pragma unroll
            for (int mt = 0; mt < 4; mt++)
#pragma unroll
                for (int np = 0; np < 4; np++) {
                    mma16(acc[mt][2 * np + 0], af[mt], &bf[np][0]);
                    mma16(acc[mt][2 * np + 1], af[mt], &bf[np][2]);
                }
        }
    }

    // Epilogue
#pragma unroll
    for (int mt = 0; mt < 4; mt++) {
        int rbase = m0 + wm + mt * 16 + g;
#pragma unroll
        for (int half = 0; half < 2; half++) {
            int r = rbase + half * 8;
            int bb2 = r >> 11, tt = r & 2047;
#pragma unroll
            for (int nt = 0; nt < 8; nt++) {
                int ccol = n0 + wn + nt * 8 + 2 * t;
                float v0 = (acc[mt][nt][half * 2 + 0] + bias[ccol]) * oscale;
                float v1 = (acc[mt][nt][half * 2 + 1] + bias[ccol + 1]) * oscale;
                if (SCATTER) {
                    int h = ccol >> 6, d = ccol & 63;
                    __half* out = (__half*)outv;
                    *(unsigned*)(out + ((size_t)((bb2 * NH + h) * TSEQ + tt)) * HDI + d)
                        = h2(v0, v1);
                } else {
                    float* out = (float*)outv;
                    *(float2*)(out + (size_t)r * EMBD + ccol) = make_float2(v0, v1);
                }
            }
        }
    }
}

__global__ __launch_bounds__(128, 2) void qkv_kernel(
    const float* __restrict__ bq, const float* __restrict__ bk,
    const float* __restrict__ bv)
{
    const __half* W; const float* bias; __half* out; float sc;
    if (blockIdx.z == 0)      { W = g_wq; bias = bq; out = g_qh; sc = 0.125f; }
    else if (blockIdx.z == 1) { W = g_wk; bias = bk; out = g_kh; sc = 1.f; }
    else                      { W = g_wv; bias = bv; out = g_vh; sc = 1.f; }
    gemm_body<1>(g_xh, W, bias, out, blockIdx.x, blockIdx.y, sc);
}

__global__ __launch_bounds__(128, 2) void proj_kernel(
    const float* __restrict__ bo, float* __restrict__ out)
{
    gemm_body<0>(g_ah, g_wo, bo, out, blockIdx.x, blockIdx.y, 1.f);
}

// ===========================================================================
// Flash attention fp16: 128 threads / 4 warps, each warp 32 q-rows (2 m-tiles).
// KV blocks 64, 3-stage cp.async (R6 pipeline). smem: Q 18KB + 3x18KB.
// ===========================================================================
#define ASTG 4608
#define ATTN_SMEM ((4608 + 3 * ASTG) * 4)   // 73728 B

__global__ __launch_bounds__(128, 2) void attn_kernel()
{
    extern __shared__ unsigned smq[];
    const uint32_t sb = (uint32_t)__cvta_generic_to_shared(smq);

    const int tid  = threadIdx.x;
    const int lane = tid & 31, wid = tid >> 5;        // 4 warps
    const int g = lane >> 2, t = lane & 3;
    const int bh = blockIdx.y, q0 = blockIdx.x * 128;
    const __half* Qg = g_qh + (size_t)bh * TSEQ * HDI;
    const __half* Kg = g_kh + (size_t)bh * TSEQ * HDI;
    const __half* Vg = g_vh + (size_t)bh * TSEQ * HDI;

    // Q: thread tid stages row tid (64 halves = 128B)
    {
        const uint32_t dQ = sb + tid * 36 * 4;
        const __half* sq = Qg + (size_t)(q0 + tid) * HDI;
#pragma unroll
        for (int i = 0; i < 8; i++) cp16(dQ + i * 16, sq + i * 8);
    }
    // K/V: 2 threads per row, 32 halves each
    const int krow = tid >> 1, ksel = tid & 1;
    const uint32_t dKo = (krow * 36) * 4 + ksel * 64;
    auto issueKV = [&](int c) {
        if (c < 32) {
            uint32_t base = sb + (4608 + (c % 3) * ASTG) * 4;
            const __half* sk = Kg + (size_t)(c * 64 + krow) * HDI + ksel * 32;
            const __half* sv = Vg + (size_t)(c * 64 + krow) * HDI + ksel * 32;
            cp16(base + dKo, sk);                cp16(base + dKo + 16, sk + 8);
            cp16(base + dKo + 32, sk + 16);      cp16(base + dKo + 48, sk + 24);
            uint32_t bv2 = base + 2304 * 4;
            cp16(bv2 + dKo, sv);                 cp16(bv2 + dKo + 16, sv + 8);
            cp16(bv2 + dKo + 32, sv + 16);       cp16(bv2 + dKo + 48, sv + 24);
        }
        cpcommit();
    };
    issueKV(0);   // group 0 completes Q + KV0
    issueKV(1);

    const uint32_t qAddr = sb +
        ((wid * 32 + (lane & 15)) * 36 + ((lane & 16) ? 4 : 0)) * 4;
    const uint32_t kLane =
        (((lane & 7) + ((lane & 16) ? 8 : 0)) * 36 + ((lane & 8) ? 4 : 0)) * 4;
    const uint32_t vLane =
        (((lane & 7) + ((lane & 8) ? 8 : 0)) * 36 + ((lane & 16) ? 4 : 0)) * 4;

    unsigned qa[2][4][4];
    float o[2][8][4];
    float m_r[2][2], l_r[2][2];
#pragma unroll
    for (int mt = 0; mt < 2; mt++) {
        m_r[mt][0] = -1e30f; m_r[mt][1] = -1e30f;
        l_r[mt][0] = 0.f;    l_r[mt][1] = 0.f;
#pragma unroll
        for (int nt = 0; nt < 8; nt++)
#pragma unroll
            for (int f = 0; f < 4; f++) o[mt][nt][f] = 0.f;
    }

    for (int jb = 0; jb < 32; jb++) {
        cpwait<1>();
        __syncthreads();
        if (jb == 0) {
#pragma unroll
            for (int mt = 0; mt < 2; mt++)
#pragma unroll
                for (int ks = 0; ks < 4; ks++)
                    ldsm4(qa[mt][ks][0], qa[mt][ks][1], qa[mt][ks][2], qa[mt][ks][3],
                          qAddr + mt * 2304 + ks * 32);
        }
        issueKV(jb + 2);

        const uint32_t kBase = sb + (4608 + (jb % 3) * ASTG) * 4 + kLane;
        const uint32_t vBase = sb + (4608 + (jb % 3) * ASTG + 2304) * 4 + vLane;

        // S = (Q/8) K^T
        float s[2][8][4];
#pragma unroll
        for (int mt = 0; mt < 2; mt++)
#pragma unroll
            for (int nt = 0; nt < 8; nt++)
#pragma unroll
                for (int f = 0; f < 4; f++) s[mt][nt][f] = 0.f;
#pragma unroll
        for (int ks = 0; ks < 4; ks++) {
            unsigned bf[4][4];
#pragma unroll
            for (int np = 0; np < 4; np++)
                ldsm4(bf[np][0], bf[np][1], bf[np][2], bf[np][3],
                      kBase + np * (16 * 36 * 4) + ks * 32);
#pragma unroll
            for (int mt = 0; mt < 2; mt++)
#pragma unroll
                for (int np = 0; np < 4; np++) {
                    mma16(s[mt][2 * np + 0], qa[mt][ks], &bf[np][0]);
                    mma16(s[mt][2 * np + 1], qa[mt][ks], &bf[np][2]);
                }
        }

        // Online softmax (per m-tile, rows g and g+8)
#pragma unroll
        for (int mt = 0; mt < 2; mt++) {
            float mx0 = -1e30f, mx1 = -1e30f;
#pragma unroll
            for (int nt = 0; nt < 8; nt++) {
                mx0 = fmaxf(mx0, fmaxf(s[mt][nt][0], s[mt][nt][1]));
                mx1 = fmaxf(mx1, fmaxf(s[mt][nt][2], s[mt][nt][3]));
            }
#pragma unroll
            for (int off = 1; off <= 2; off <<= 1) {
                mx0 = fmaxf(mx0, __shfl_xor_sync(0xffffffffu, mx0, off));
                mx1 = fmaxf(mx1, __shfl_xor_sync(0xffffffffu, mx1, off));
            }
            float M0 = fmaxf(m_r[mt][0], mx0), M1 = fmaxf(m_r[mt][1], mx1);
            float al0 = __expf(m_r[mt][0] - M0), al1 = __expf(m_r[mt][1] - M1);
            float rs0 = 0.f, rs1 = 0.f;
#pragma unroll
            for (int nt = 0; nt < 8; nt++) {
                s[mt][nt][0] = __expf(s[mt][nt][0] - M0); rs0 += s[mt][nt][0];
                s[mt][nt][1] = __expf(s[mt][nt][1] - M0); rs0 += s[mt][nt][1];
                s[mt][nt][2] = __expf(s[mt][nt][2] - M1); rs1 += s[mt][nt][2];
                s[mt][nt][3] = __expf(s[mt][nt][3] - M1); rs1 += s[mt][nt][3];
            }
#pragma unroll
            for (int off = 1; off <= 2; off <<= 1) {
                rs0 += __shfl_xor_sync(0xffffffffu, rs0, off);
                rs1 += __shfl_xor_sync(0xffffffffu, rs1, off);
            }
            l_r[mt][0] = l_r[mt][0] * al0 + rs0;
            l_r[mt][1] = l_r[mt][1] * al1 + rs1;
            m_r[mt][0] = M0; m_r[mt][1] = M1;
#pragma unroll
            for (int nt = 0; nt < 8; nt++) {
                o[mt][nt][0] *= al0; o[mt][nt][1] *= al0;
                o[mt][nt][2] *= al1; o[mt][nt][3] *= al1;
            }
        }

        // O += P V
#pragma unroll
        for (int ks = 0; ks < 4; ks++) {
            unsigned af[2][4];
#pragma unroll
            for (int mt = 0; mt < 2; mt++) {
                af[mt][0] = h2(s[mt][2 * ks][0],     s[mt][2 * ks][1]);
                af[mt][1] = h2(s[mt][2 * ks][2],     s[mt][2 * ks][3]);
                af[mt][2] = h2(s[mt][2 * ks + 1][0], s[mt][2 * ks + 1][1]);
                af[mt][3] = h2(s[mt][2 * ks + 1][2], s[mt][2 * ks + 1][3]);
            }
#pragma unroll
            for (int np = 0; np < 4; np++) {
                unsigned vf[4];
                ldsm4t(vf[0], vf[1], vf[2], vf[3],
                       vBase + ks * (16 * 36 * 4) + np * 32);
#pragma unroll
                for (int mt = 0; mt < 2; mt++) {
                    mma16(o[mt][2 * np + 0], af[mt], &vf[0]);
                    mma16(o[mt][2 * np + 1], af[mt], &vf[2]);
                }
            }
        }
    }

    // Write back fp16 [B,T,E]
    const int b = bh >> 4, h = bh & 15;
#pragma unroll
    for (int mt = 0; mt < 2; mt++) {
        float inv0 = 1.f / l_r[mt][0], inv1 = 1.f / l_r[mt][1];
        int r0 = q0 + wid * 32 + mt * 16 + g, r1 = r0 + 8;
#pragma unroll
        for (int nt = 0; nt < 8; nt++) {
            int c = h * HDI + nt * 8 + 2 * t;
            *(unsigned*)(g_ah + (size_t)(b * TSEQ + r0) * EMBD + c)
                = h2(o[mt][nt][0] * inv0, o[mt][nt][1] * inv0);
            *(unsigned*)(g_ah + (size_t)(b * TSEQ + r1) * EMBD + c)
                = h2(o[mt][nt][2] * inv1, o[mt][nt][3] * inv1);
        }
    }
}

// ---------------------------------------------------------------------------
extern "C" void kernel_launch(void* const* d_in, const int* in_sizes, int n_in,
                              void* d_out, int out_size)
{
    const float* x  = (const float*)d_in[0];
    const float* Wq = (const float*)d_in[1];
    const float* bq = (const float*)d_in[2];
    const float* Wk = (const float*)d_in[3];
    const float* bk = (const float*)d_in[4];
    const float* Wv = (const float*)d_in[5];
    const float* bv = (const float*)d_in[6];
    const float* Wo = (const float*)d_in[7];
    const float* bo = (const float*)d_in[8];
    float* out = (float*)d_out;

    static int inited = 0;
    if (!inited) {
        cudaFuncSetAttribute(qkv_kernel,  cudaFuncAttributeMaxDynamicSharedMemorySize, GEMM_SMEM);
        cudaFuncSetAttribute(proj_kernel, cudaFuncAttributeMaxDynamicSharedMemorySize, GEMM_SMEM);
        cudaFuncSetAttribute(attn_kernel, cudaFuncAttributeMaxDynamicSharedMemorySize, ATTN_SMEM);
        inited = 1;
    }

    cvt_all<<<dim3(128, 5), 256>>>(x, Wq, Wk, Wv, Wo);

    dim3 gq(M_TOT / 128, EMBD / 128, 3);
    qkv_kernel<<<gq, 128, GEMM_SMEM>>>(bq, bk, bv);

    dim3 ga(TSEQ / 128, NB * NH);
    attn_kernel<<<ga, 128, ATTN_SMEM>>>();

    dim3 go(M_TOT / 128, EMBD / 128);
    proj_kernel<<<go, 128, GEMM_SMEM>>>(bo, out);
}

// round 15
// speedup vs baseline: 1.2864x; 1.2864x over previous
#include <cuda_runtime.h>
#include <cuda_fp16.h>
#include <cstdint>

#define M_TOT 8192
#define EMBD  1024
#define TSEQ  2048
#define NB    4
#define NH    16
#define HDI   64

// fp16 scratch
__device__ __half g_xh[M_TOT * EMBD];
__device__ __half g_wq[EMBD * EMBD];
__device__ __half g_wk[EMBD * EMBD];
__device__ __half g_wv[EMBD * EMBD];
__device__ __half g_wo[EMBD * EMBD];
__device__ __half g_qh[M_TOT * EMBD];   // [B,H,T,hd], pre-scaled by 0.125*log2(e)
__device__ __half g_kh[M_TOT * EMBD];   // [B,H,T,hd]
__device__ __half g_vh[M_TOT * EMBD];   // [B,H,T,hd]
__device__ __half g_ah[M_TOT * EMBD];   // [B,T,E]

__device__ __forceinline__ unsigned h2(float a, float b) {
    __half2 h = __floats2half2_rn(a, b);
    return *(unsigned*)&h;
}
__device__ __forceinline__ unsigned ex2h2(unsigned x) {
    unsigned r; asm("ex2.approx.f16x2 %0, %1;" : "=r"(r) : "r"(x)); return r;
}
__device__ __forceinline__ float fex2(float x) {
    float r; asm("ex2.approx.ftz.f32 %0, %1;" : "=f"(r) : "f"(x)); return r;
}
__device__ __forceinline__ float2 h2f2(unsigned x) {
    __half2 h = *(__half2*)&x;
    return __half22float2(h);
}
__device__ __forceinline__ void mma16(float* d, const unsigned* a, const unsigned* b) {
    asm volatile("mma.sync.aligned.m16n8k16.row.col.f32.f16.f16.f32 "
        "{%0,%1,%2,%3}, {%4,%5,%6,%7}, {%8,%9}, {%0,%1,%2,%3};"
        : "+f"(d[0]), "+f"(d[1]), "+f"(d[2]), "+f"(d[3])
        : "r"(a[0]), "r"(a[1]), "r"(a[2]), "r"(a[3]), "r"(b[0]), "r"(b[1]));
}
__device__ __forceinline__ void cp16(uint32_t dst, const void* src) {
    asm volatile("cp.async.cg.shared.global [%0], [%1], 16;" :: "r"(dst), "l"(src));
}
__device__ __forceinline__ void cpcommit() { asm volatile("cp.async.commit_group;"); }
template<int N> __device__ __forceinline__ void cpwait() {
    asm volatile("cp.async.wait_group %0;" :: "n"(N));
}
__device__ __forceinline__ void ldsm4(unsigned& r0, unsigned& r1, unsigned& r2,
                                      unsigned& r3, uint32_t a) {
    asm volatile("ldmatrix.sync.aligned.m8n8.x4.shared.b16 {%0,%1,%2,%3}, [%4];"
                 : "=r"(r0), "=r"(r1), "=r"(r2), "=r"(r3) : "r"(a));
}
__device__ __forceinline__ void ldsm4t(unsigned& r0, unsigned& r1, unsigned& r2,
                                       unsigned& r3, uint32_t a) {
    asm volatile("ldmatrix.sync.aligned.m8n8.x4.trans.shared.b16 {%0,%1,%2,%3}, [%4];"
                 : "=r"(r0), "=r"(r1), "=r"(r2), "=r"(r3) : "r"(a));
}

// ===========================================================================
// fp32 -> fp16 conversion of inputs
// ===========================================================================
__global__ __launch_bounds__(256) void cvt_all(
    const float* __restrict__ x, const float* __restrict__ wq,
    const float* __restrict__ wk, const float* __restrict__ wv,
    const float* __restrict__ wo)
{
    const float* src; __half* dst; int n;
    switch (blockIdx.y) {
        case 0:  src = x;  dst = g_xh; n = M_TOT * EMBD; break;
        case 1:  src = wq; dst = g_wq; n = EMBD * EMBD;  break;
        case 2:  src = wk; dst = g_wk; n = EMBD * EMBD;  break;
        case 3:  src = wv; dst = g_wv; n = EMBD * EMBD;  break;
        default: src = wo; dst = g_wo; n = EMBD * EMBD;  break;
    }
    int stride = gridDim.x * blockDim.x * 8;
    for (int i = (blockIdx.x * blockDim.x + threadIdx.x) * 8; i < n; i += stride) {
        float4 a = *(const float4*)(src + i);
        float4 b = *(const float4*)(src + i + 4);
        uint4 o;
        o.x = h2(a.x, a.y); o.y = h2(a.z, a.w);
        o.z = h2(b.x, b.y); o.w = h2(b.z, b.w);
        *(uint4*)(dst + i) = o;
    }
}

// ===========================================================================
// fp16 GEMM: 128x128 tile, k-chunk 32, 5-stage cp.async, wait<3>.
// ===========================================================================
#define GSTG 5120                    // words per stage
#define GEMM_SMEM (5 * GSTG * 4)     // 102400 B

template<int SCATTER>
__device__ __forceinline__ void gemm_body(
    const __half* __restrict__ A, const __half* __restrict__ Bw,
    const float* __restrict__ bias, void* __restrict__ outv,
    int bx, int by, float oscale)
{
    extern __shared__ unsigned smu[];
    const uint32_t sb = (uint32_t)__cvta_generic_to_shared(smu);

    const int tid  = threadIdx.x;
    const int lane = tid & 31, wid = tid >> 5;
    const int g = lane >> 2, t = lane & 3;
    const int wm = (wid & 3) * 32, wn = (wid >> 2) * 64;
    const int m0 = bx * 128, n0 = by * 128;

    const int crow = tid >> 1, csel = tid & 1;
    const __half* gA = A  + (size_t)(m0 + crow) * EMBD + csel * 16;
    const __half* gB = Bw + (size_t)(n0 + crow) * EMBD + csel * 16;
    const uint32_t dA = sb + (crow * 20 + csel * 8) * 4;
    const uint32_t dB = dA + 2560 * 4;

    auto issue = [&](int c) {
        if (c < 32) {
            uint32_t so = (uint32_t)(c % 5) * (GSTG * 4);
            const __half* sa = gA + c * 32;
            const __half* sbp = gB + c * 32;
            cp16(dA + so, sa);       cp16(dA + so + 16, sa + 8);
            cp16(dB + so, sbp);      cp16(dB + so + 16, sbp + 8);
        }
        cpcommit();
    };
    issue(0); issue(1); issue(2); issue(3);

    const uint32_t aAddr = sb +
        ((wm + (lane & 15)) * 20 + ((lane & 16) ? 4 : 0)) * 4;
    const uint32_t bAddr = sb + 2560 * 4 +
        ((wn + (lane & 7) + ((lane & 16) ? 8 : 0)) * 20 + ((lane & 8) ? 4 : 0)) * 4;

    float acc[2][8][4];
#pragma unroll
    for (int mt = 0; mt < 2; mt++)
#pragma unroll
        for (int nt = 0; nt < 8; nt++)
#pragma unroll
            for (int f = 0; f < 4; f++) acc[mt][nt][f] = 0.f;

    for (int c = 0; c < 32; c++) {
        cpwait<3>();
        __syncthreads();
        issue(c + 4);
        const uint32_t so = (uint32_t)(c % 5) * (GSTG * 4);
#pragma unroll
        for (int ks = 0; ks < 2; ks++) {
            unsigned af[2][4], bf[4][4];
            ldsm4(af[0][0], af[0][1], af[0][2], af[0][3], aAddr + so + ks * 32);
            ldsm4(af[1][0], af[1][1], af[1][2], af[1][3], aAddr + so + 16 * 80 + ks * 32);
#pragma unroll
            for (int np = 0; np < 4; np++)
                ldsm4(bf[np][0], bf[np][1], bf[np][2], bf[np][3],
                      bAddr + so + np * (16 * 80) + ks * 32);
#pragma unroll
            for (int mt = 0; mt < 2; mt++)
#pragma unroll
                for (int np = 0; np < 4; np++) {
                    mma16(acc[mt][2 * np + 0], af[mt], &bf[np][0]);
                    mma16(acc[mt][2 * np + 1], af[mt], &bf[np][2]);
                }
        }
    }

    // Epilogue
#pragma unroll
    for (int mt = 0; mt < 2; mt++) {
        int rbase = m0 + wm + mt * 16 + g;
#pragma unroll
        for (int half = 0; half < 2; half++) {
            int r = rbase + half * 8;
            int bb2 = r >> 11, tt = r & 2047;
#pragma unroll
            for (int nt = 0; nt < 8; nt++) {
                int ccol = n0 + wn + nt * 8 + 2 * t;
                float v0 = (acc[mt][nt][half * 2 + 0] + bias[ccol]) * oscale;
                float v1 = (acc[mt][nt][half * 2 + 1] + bias[ccol + 1]) * oscale;
                if (SCATTER) {
                    int h = ccol >> 6, d = ccol & 63;
                    __half* out = (__half*)outv;
                    *(unsigned*)(out + ((size_t)((bb2 * NH + h) * TSEQ + tt)) * HDI + d)
                        = h2(v0, v1);
                } else {
                    float* out = (float*)outv;
                    *(float2*)(out + (size_t)r * EMBD + ccol) = make_float2(v0, v1);
                }
            }
        }
    }
}

__global__ __launch_bounds__(256, 2) void qkv_kernel(
    const float* __restrict__ bq, const float* __restrict__ bk,
    const float* __restrict__ bv)
{
    const __half* W; const float* bias; __half* out; float sc;
    if (blockIdx.z == 0)      { W = g_wq; bias = bq; out = g_qh;
                                sc = 0.125f * 1.4426950408889634f; }   // 1/8 * log2(e)
    else if (blockIdx.z == 1) { W = g_wk; bias = bk; out = g_kh; sc = 1.f; }
    else                      { W = g_wv; bias = bv; out = g_vh; sc = 1.f; }
    gemm_body<1>(g_xh, W, bias, out, blockIdx.x, blockIdx.y, sc);
}

__global__ __launch_bounds__(256, 2) void proj_kernel(
    const float* __restrict__ bo, float* __restrict__ out)
{
    gemm_body<0>(g_ah, g_wo, bo, out, blockIdx.x, blockIdx.y, 1.f);
}

// ===========================================================================
// Flash attention fp16, base-2 softmax (ex2.approx.f16x2), 3-stage KV pipeline.
// ===========================================================================
#define ASTG 4608
#define ATTN_SMEM ((4608 + 3 * ASTG) * 4)   // 73728 B

__global__ __launch_bounds__(256, 2) void attn_kernel()
{
    extern __shared__ unsigned smq[];
    const uint32_t sb = (uint32_t)__cvta_generic_to_shared(smq);

    const int tid  = threadIdx.x;
    const int lane = tid & 31, wid = tid >> 5;
    const int g = lane >> 2, t = lane & 3;
    const int bh = blockIdx.y, q0 = blockIdx.x * 128;
    const __half* Qg = g_qh + (size_t)bh * TSEQ * HDI;
    const __half* Kg = g_kh + (size_t)bh * TSEQ * HDI;
    const __half* Vg = g_vh + (size_t)bh * TSEQ * HDI;

    const int qrow = tid >> 1, qsel = tid & 1;
    const int krow = tid >> 2, ksel = tid & 3;
    const uint32_t dQ = sb + (qrow * 36 + qsel * 16) * 4;
    const uint32_t dKo = (krow * 36 + ksel * 8) * 4;

    {
        const __half* sq = Qg + (size_t)(q0 + qrow) * HDI + qsel * 32;
        cp16(dQ, sq); cp16(dQ + 16, sq + 8);
        cp16(dQ + 32, sq + 16); cp16(dQ + 48, sq + 24);
    }
    auto issueKV = [&](int c) {
        if (c < 32) {
            uint32_t base = sb + (4608 + (c % 3) * ASTG) * 4;
            const __half* sk = Kg + (size_t)(c * 64 + krow) * HDI + ksel * 16;
            const __half* sv = Vg + (size_t)(c * 64 + krow) * HDI + ksel * 16;
            cp16(base + dKo, sk);               cp16(base + dKo + 16, sk + 8);
            cp16(base + 2304 * 4 + dKo, sv);    cp16(base + 2304 * 4 + dKo + 16, sv + 8);
        }
        cpcommit();
    };
    issueKV(0);   // group 0 completes Q + KV0
    issueKV(1);

    const uint32_t qAddr = sb +
        ((wid * 16 + (lane & 15)) * 36 + ((lane & 16) ? 4 : 0)) * 4;
    const uint32_t kLane =
        (((lane & 7) + ((lane & 16) ? 8 : 0)) * 36 + ((lane & 8) ? 4 : 0)) * 4;
    const uint32_t vLane =
        (((lane & 7) + ((lane & 8) ? 8 : 0)) * 36 + ((lane & 16) ? 4 : 0)) * 4;

    unsigned qa[4][4];
    float o[8][4];
#pragma unroll
    for (int nt = 0; nt < 8; nt++)
#pragma unroll
        for (int f = 0; f < 4; f++) o[nt][f] = 0.f;
    float m0r = -1e30f, m1r = -1e30f, l0 = 0.f, l1 = 0.f;

    for (int jb = 0; jb < 32; jb++) {
        cpwait<1>();
        __syncthreads();
        if (jb == 0) {
#pragma unroll
            for (int ks = 0; ks < 4; ks++)
                ldsm4(qa[ks][0], qa[ks][1], qa[ks][2], qa[ks][3], qAddr + ks * 32);
        }
        issueKV(jb + 2);

        const uint32_t kBase = sb + (4608 + (jb % 3) * ASTG) * 4 + kLane;
        const uint32_t vBase = sb + (4608 + (jb % 3) * ASTG + 2304) * 4 + vLane;

        // S = Q K^T  (base-2 logits)
        float s[8][4];
#pragma unroll
        for (int nt = 0; nt < 8; nt++)
#pragma unroll
            for (int f = 0; f < 4; f++) s[nt][f] = 0.f;
#pragma unroll
        for (int ks = 0; ks < 4; ks++) {
            unsigned bf[4][4];
#pragma unroll
            for (int np = 0; np < 4; np++)
                ldsm4(bf[np][0], bf[np][1], bf[np][2], bf[np][3],
                      kBase + np * (16 * 36 * 4) + ks * 32);
#pragma unroll
            for (int np = 0; np < 4; np++) {
                mma16(s[2 * np + 0], qa[ks], &bf[np][0]);
                mma16(s[2 * np + 1], qa[ks], &bf[np][2]);
            }
        }

        // Online softmax (exp2 domain)
        float mx0 = -1e30f, mx1 = -1e30f;
#pragma unroll
        for (int nt = 0; nt < 8; nt++) {
            mx0 = fmaxf(mx0, fmaxf(s[nt][0], s[nt][1]));
            mx1 = fmaxf(mx1, fmaxf(s[nt][2], s[nt][3]));
        }
#pragma unroll
        for (int off = 1; off <= 2; off <<= 1) {
            mx0 = fmaxf(mx0, __shfl_xor_sync(0xffffffffu, mx0, off));
            mx1 = fmaxf(mx1, __shfl_xor_sync(0xffffffffu, mx1, off));
        }
        float M0 = fmaxf(m0r, mx0), M1 = fmaxf(m1r, mx1);
        float al0 = fex2(m0r - M0), al1 = fex2(m1r - M1);

        // P = 2^(S - M) as f16x2; these ARE the PV A-fragment halves.
        unsigned ph[8][2];
        float rs0 = 0.f, rs1 = 0.f;
#pragma unroll
        for (int nt = 0; nt < 8; nt++) {
            ph[nt][0] = ex2h2(h2(s[nt][0] - M0, s[nt][1] - M0));
            ph[nt][1] = ex2h2(h2(s[nt][2] - M1, s[nt][3] - M1));
            float2 fa = h2f2(ph[nt][0]); rs0 += fa.x + fa.y;
            float2 fb = h2f2(ph[nt][1]); rs1 += fb.x + fb.y;
        }
        // REQUIRED: reduce row-sums across the 4 t-lanes of each row (bug in R14)
#pragma unroll
        for (int off = 1; off <= 2; off <<= 1) {
            rs0 += __shfl_xor_sync(0xffffffffu, rs0, off);
            rs1 += __shfl_xor_sync(0xffffffffu, rs1, off);
        }
        l0 = l0 * al0 + rs0; l1 = l1 * al1 + rs1;
        m0r = M0; m1r = M1;
#pragma unroll
        for (int nt = 0; nt < 8; nt++) {
            o[nt][0] *= al0; o[nt][1] *= al0;
            o[nt][2] *= al1; o[nt][3] *= al1;
        }

        // O += P V
#pragma unroll
        for (int ks = 0; ks < 4; ks++) {
            unsigned af[4];
            af[0] = ph[2 * ks][0];
            af[1] = ph[2 * ks][1];
            af[2] = ph[2 * ks + 1][0];
            af[3] = ph[2 * ks + 1][1];
#pragma unroll
            for (int np = 0; np < 4; np++) {
                unsigned vf[4];
                ldsm4t(vf[0], vf[1], vf[2], vf[3],
                       vBase + ks * (16 * 36 * 4) + np * 32);
                mma16(o[2 * np + 0], af, &vf[0]);
                mma16(o[2 * np + 1], af, &vf[2]);
            }
        }
    }

    const int b = bh >> 4, h = bh & 15;
    float inv0 = 1.f / l0, inv1 = 1.f / l1;
    int r0 = q0 + wid * 16 + g, r1 = r0 + 8;
#pragma unroll
    for (int nt = 0; nt < 8; nt++) {
        int c = h * HDI + nt * 8 + 2 * t;
        *(unsigned*)(g_ah + (size_t)(b * TSEQ + r0) * EMBD + c)
            = h2(o[nt][0] * inv0, o[nt][1] * inv0);
        *(unsigned*)(g_ah + (size_t)(b * TSEQ + r1) * EMBD + c)
            = h2(o[nt][2] * inv1, o[nt][3] * inv1);
    }
}

// ---------------------------------------------------------------------------
extern "C" void kernel_launch(void* const* d_in, const int* in_sizes, int n_in,
                              void* d_out, int out_size)
{
    const float* x  = (const float*)d_in[0];
    const float* Wq = (const float*)d_in[1];
    const float* bq = (const float*)d_in[2];
    const float* Wk = (const float*)d_in[3];
    const float* bk = (const float*)d_in[4];
    const float* Wv = (const float*)d_in[5];
    const float* bv = (const float*)d_in[6];
    const float* Wo = (const float*)d_in[7];
    const float* bo = (const float*)d_in[8];
    float* out = (float*)d_out;

    static int inited = 0;
    if (!inited) {
        cudaFuncSetAttribute(qkv_kernel,  cudaFuncAttributeMaxDynamicSharedMemorySize, GEMM_SMEM);
        cudaFuncSetAttribute(proj_kernel, cudaFuncAttributeMaxDynamicSharedMemorySize, GEMM_SMEM);
        cudaFuncSetAttribute(attn_kernel, cudaFuncAttributeMaxDynamicSharedMemorySize, ATTN_SMEM);
        inited = 1;
    }

    cvt_all<<<dim3(128, 5), 256>>>(x, Wq, Wk, Wv, Wo);

    dim3 gq(M_TOT / 128, EMBD / 128, 3);
    qkv_kernel<<<gq, 256, GEMM_SMEM>>>(bq, bk, bv);

    dim3 ga(TSEQ / 128, NB * NH);
    attn_kernel<<<ga, 256, ATTN_SMEM>>>();

    dim3 go(M_TOT / 128, EMBD / 128);
    proj_kernel<<<go, 256, GEMM_SMEM>>>(bo, out);
}

// round 16
// speedup vs baseline: 1.3134x; 1.0209x over previous
#include <cuda_runtime.h>
#include <cuda_fp16.h>
#include <cstdint>

#define M_TOT 8192
#define EMBD  1024
#define TSEQ  2048
#define NB    4
#define NH    16
#define HDI   64

// fp16 scratch
__device__ __half g_xh[M_TOT * EMBD];
__device__ __half g_wq[EMBD * EMBD];
__device__ __half g_wk[EMBD * EMBD];
__device__ __half g_wv[EMBD * EMBD];
__device__ __half g_wo[EMBD * EMBD];
__device__ __half g_qh[M_TOT * EMBD];   // [B,H,T,hd], pre-scaled by 0.125*log2(e)
__device__ __half g_kh[M_TOT * EMBD];   // [B,H,T,hd]
__device__ __half g_vh[M_TOT * EMBD];   // [B,H,T,hd]
__device__ __half g_ah[M_TOT * EMBD];   // [B,T,E]

__device__ __forceinline__ unsigned h2(float a, float b) {
    __half2 h = __floats2half2_rn(a, b);
    return *(unsigned*)&h;
}
__device__ __forceinline__ unsigned ex2h2(unsigned x) {
    unsigned r; asm("ex2.approx.f16x2 %0, %1;" : "=r"(r) : "r"(x)); return r;
}
__device__ __forceinline__ float fex2(float x) {
    float r; asm("ex2.approx.ftz.f32 %0, %1;" : "=f"(r) : "f"(x)); return r;
}
__device__ __forceinline__ void mma16(float* d, const unsigned* a, const unsigned* b) {
    asm volatile("mma.sync.aligned.m16n8k16.row.col.f32.f16.f16.f32 "
        "{%0,%1,%2,%3}, {%4,%5,%6,%7}, {%8,%9}, {%0,%1,%2,%3};"
        : "+f"(d[0]), "+f"(d[1]), "+f"(d[2]), "+f"(d[3])
        : "r"(a[0]), "r"(a[1]), "r"(a[2]), "r"(a[3]), "r"(b[0]), "r"(b[1]));
}
__device__ __forceinline__ void cp16(uint32_t dst, const void* src) {
    asm volatile("cp.async.cg.shared.global [%0], [%1], 16;" :: "r"(dst), "l"(src));
}
__device__ __forceinline__ void cpcommit() { asm volatile("cp.async.commit_group;"); }
template<int N> __device__ __forceinline__ void cpwait() {
    asm volatile("cp.async.wait_group %0;" :: "n"(N));
}
__device__ __forceinline__ void ldsm4(unsigned& r0, unsigned& r1, unsigned& r2,
                                      unsigned& r3, uint32_t a) {
    asm volatile("ldmatrix.sync.aligned.m8n8.x4.shared.b16 {%0,%1,%2,%3}, [%4];"
                 : "=r"(r0), "=r"(r1), "=r"(r2), "=r"(r3) : "r"(a));
}
__device__ __forceinline__ void ldsm4t(unsigned& r0, unsigned& r1, unsigned& r2,
                                       unsigned& r3, uint32_t a) {
    asm volatile("ldmatrix.sync.aligned.m8n8.x4.trans.shared.b16 {%0,%1,%2,%3}, [%4];"
                 : "=r"(r0), "=r"(r1), "=r"(r2), "=r"(r3) : "r"(a));
}

// ===========================================================================
// fp32 -> fp16 conversion of inputs
// ===========================================================================
__global__ __launch_bounds__(256) void cvt_all(
    const float* __restrict__ x, const float* __restrict__ wq,
    const float* __restrict__ wk, const float* __restrict__ wv,
    const float* __restrict__ wo)
{
    const float* src; __half* dst; int n;
    switch (blockIdx.y) {
        case 0:  src = x;  dst = g_xh; n = M_TOT * EMBD; break;
        case 1:  src = wq; dst = g_wq; n = EMBD * EMBD;  break;
        case 2:  src = wk; dst = g_wk; n = EMBD * EMBD;  break;
        case 3:  src = wv; dst = g_wv; n = EMBD * EMBD;  break;
        default: src = wo; dst = g_wo; n = EMBD * EMBD;  break;
    }
    int stride = gridDim.x * blockDim.x * 8;
    for (int i = (blockIdx.x * blockDim.x + threadIdx.x) * 8; i < n; i += stride) {
        float4 a = *(const float4*)(src + i);
        float4 b = *(const float4*)(src + i + 4);
        uint4 o;
        o.x = h2(a.x, a.y); o.y = h2(a.z, a.w);
        o.z = h2(b.x, b.y); o.w = h2(b.z, b.w);
        *(uint4*)(dst + i) = o;
    }
}

// ===========================================================================
// fp16 GEMM: 128x128 tile, k-chunk 32, 5-stage cp.async, wait<3>. (R15, unchanged)
// ===========================================================================
#define GSTG 5120                    // words per stage
#define GEMM_SMEM (5 * GSTG * 4)     // 102400 B

template<int SCATTER>
__device__ __forceinline__ void gemm_body(
    const __half* __restrict__ A, const __half* __restrict__ Bw,
    const float* __restrict__ bias, void* __restrict__ outv,
    int bx, int by, float oscale)
{
    extern __shared__ unsigned smu[];
    const uint32_t sb = (uint32_t)__cvta_generic_to_shared(smu);

    const int tid  = threadIdx.x;
    const int lane = tid & 31, wid = tid >> 5;
    const int g = lane >> 2, t = lane & 3;
    const int wm = (wid & 3) * 32, wn = (wid >> 2) * 64;
    const int m0 = bx * 128, n0 = by * 128;

    const int crow = tid >> 1, csel = tid & 1;
    const __half* gA = A  + (size_t)(m0 + crow) * EMBD + csel * 16;
    const __half* gB = Bw + (size_t)(n0 + crow) * EMBD + csel * 16;
    const uint32_t dA = sb + (crow * 20 + csel * 8) * 4;
    const uint32_t dB = dA + 2560 * 4;

    auto issue = [&](int c) {
        if (c < 32) {
            uint32_t so = (uint32_t)(c % 5) * (GSTG * 4);
            const __half* sa = gA + c * 32;
            const __half* sbp = gB + c * 32;
            cp16(dA + so, sa);       cp16(dA + so + 16, sa + 8);
            cp16(dB + so, sbp);      cp16(dB + so + 16, sbp + 8);
        }
        cpcommit();
    };
    issue(0); issue(1); issue(2); issue(3);

    const uint32_t aAddr = sb +
        ((wm + (lane & 15)) * 20 + ((lane & 16) ? 4 : 0)) * 4;
    const uint32_t bAddr = sb + 2560 * 4 +
        ((wn + (lane & 7) + ((lane & 16) ? 8 : 0)) * 20 + ((lane & 8) ? 4 : 0)) * 4;

    float acc[2][8][4];
#pragma unroll
    for (int mt = 0; mt < 2; mt++)
#pragma unroll
        for (int nt = 0; nt < 8; nt++)
#pragma unroll
            for (int f = 0; f < 4; f++) acc[mt][nt][f] = 0.f;

    for (int c = 0; c < 32; c++) {
        cpwait<3>();
        __syncthreads();
        issue(c + 4);
        const uint32_t so = (uint32_t)(c % 5) * (GSTG * 4);
#pragma unroll
        for (int ks = 0; ks < 2; ks++) {
            unsigned af[2][4], bf[4][4];
            ldsm4(af[0][0], af[0][1], af[0][2], af[0][3], aAddr + so + ks * 32);
            ldsm4(af[1][0], af[1][1], af[1][2], af[1][3], aAddr + so + 16 * 80 + ks * 32);
#pragma unroll
            for (int np = 0; np < 4; np++)
                ldsm4(bf[np][0], bf[np][1], bf[np][2], bf[np][3],
                      bAddr + so + np * (16 * 80) + ks * 32);
#pragma unroll
            for (int mt = 0; mt < 2; mt++)
#pragma unroll
                for (int np = 0; np < 4; np++) {
                    mma16(acc[mt][2 * np + 0], af[mt], &bf[np][0]);
                    mma16(acc[mt][2 * np + 1], af[mt], &bf[np][2]);
                }
        }
    }

    // Epilogue
#pragma unroll
    for (int mt = 0; mt < 2; mt++) {
        int rbase = m0 + wm + mt * 16 + g;
#pragma unroll
        for (int half = 0; half < 2; half++) {
            int r = rbase + half * 8;
            int bb2 = r >> 11, tt = r & 2047;
#pragma unroll
            for (int nt = 0; nt < 8; nt++) {
                int ccol = n0 + wn + nt * 8 + 2 * t;
                float v0 = (acc[mt][nt][half * 2 + 0] + bias[ccol]) * oscale;
                float v1 = (acc[mt][nt][half * 2 + 1] + bias[ccol + 1]) * oscale;
                if (SCATTER) {
                    int h = ccol >> 6, d = ccol & 63;
                    __half* out = (__half*)outv;
                    *(unsigned*)(out + ((size_t)((bb2 * NH + h) * TSEQ + tt)) * HDI + d)
                        = h2(v0, v1);
                } else {
                    float* out = (float*)outv;
                    *(float2*)(out + (size_t)r * EMBD + ccol) = make_float2(v0, v1);
                }
            }
        }
    }
}

__global__ __launch_bounds__(256, 2) void qkv_kernel(
    const float* __restrict__ bq, const float* __restrict__ bk,
    const float* __restrict__ bv)
{
    const __half* W; const float* bias; __half* out; float sc;
    if (blockIdx.z == 0)      { W = g_wq; bias = bq; out = g_qh;
                                sc = 0.125f * 1.4426950408889634f; }   // 1/8 * log2(e)
    else if (blockIdx.z == 1) { W = g_wk; bias = bk; out = g_kh; sc = 1.f; }
    else                      { W = g_wv; bias = bv; out = g_vh; sc = 1.f; }
    gemm_body<1>(g_xh, W, bias, out, blockIdx.x, blockIdx.y, sc);
}

__global__ __launch_bounds__(256, 2) void proj_kernel(
    const float* __restrict__ bo, float* __restrict__ out)
{
    gemm_body<0>(g_ah, g_wo, bo, out, blockIdx.x, blockIdx.y, 1.f);
}

// ===========================================================================
// Flash attention fp16, base-2 softmax. Row-sums computed by an extra mma
// against a constant all-ones B fragment (P·1 = rowsum) — no adds/cvts/shfls.
// 3-stage KV cp.async pipeline.
// ===========================================================================
#define ASTG 4608
#define ATTN_SMEM ((4608 + 3 * ASTG) * 4)   // 73728 B

__global__ __launch_bounds__(256, 2) void attn_kernel()
{
    extern __shared__ unsigned smq[];
    const uint32_t sb = (uint32_t)__cvta_generic_to_shared(smq);

    const int tid  = threadIdx.x;
    const int lane = tid & 31, wid = tid >> 5;
    const int g = lane >> 2, t = lane & 3;
    const int bh = blockIdx.y, q0 = blockIdx.x * 128;
    const __half* Qg = g_qh + (size_t)bh * TSEQ * HDI;
    const __half* Kg = g_kh + (size_t)bh * TSEQ * HDI;
    const __half* Vg = g_vh + (size_t)bh * TSEQ * HDI;

    const int qrow = tid >> 1, qsel = tid & 1;
    const int krow = tid >> 2, ksel = tid & 3;
    const uint32_t dQ = sb + (qrow * 36 + qsel * 16) * 4;
    const uint32_t dKo = (krow * 36 + ksel * 8) * 4;

    {
        const __half* sq = Qg + (size_t)(q0 + qrow) * HDI + qsel * 32;
        cp16(dQ, sq); cp16(dQ + 16, sq + 8);
        cp16(dQ + 32, sq + 16); cp16(dQ + 48, sq + 24);
    }
    auto issueKV = [&](int c) {
        if (c < 32) {
            uint32_t base = sb + (4608 + (c % 3) * ASTG) * 4;
            const __half* sk = Kg + (size_t)(c * 64 + krow) * HDI + ksel * 16;
            const __half* sv = Vg + (size_t)(c * 64 + krow) * HDI + ksel * 16;
            cp16(base + dKo, sk);               cp16(base + dKo + 16, sk + 8);
            cp16(base + 2304 * 4 + dKo, sv);    cp16(base + 2304 * 4 + dKo + 16, sv + 8);
        }
        cpcommit();
    };
    issueKV(0);   // group 0 completes Q + KV0
    issueKV(1);

    const uint32_t qAddr = sb +
        ((wid * 16 + (lane & 15)) * 36 + ((lane & 16) ? 4 : 0)) * 4;
    const uint32_t kLane =
        (((lane & 7) + ((lane & 16) ? 8 : 0)) * 36 + ((lane & 8) ? 4 : 0)) * 4;
    const uint32_t vLane =
        (((lane & 7) + ((lane & 8) ? 8 : 0)) * 36 + ((lane & 16) ? 4 : 0)) * 4;

    unsigned qa[4][4];
    float o[8][4];
#pragma unroll
    for (int nt = 0; nt < 8; nt++)
#pragma unroll
        for (int f = 0; f < 4; f++) o[nt][f] = 0.f;
    float m0r = -1e30f, m1r = -1e30f, l0 = 0.f, l1 = 0.f;

    const unsigned bones[2] = {0x3C003C00u, 0x3C003C00u};   // f16x2(1,1)

    for (int jb = 0; jb < 32; jb++) {
        cpwait<1>();
        __syncthreads();
        if (jb == 0) {
#pragma unroll
            for (int ks = 0; ks < 4; ks++)
                ldsm4(qa[ks][0], qa[ks][1], qa[ks][2], qa[ks][3], qAddr + ks * 32);
        }
        issueKV(jb + 2);

        const uint32_t kBase = sb + (4608 + (jb % 3) * ASTG) * 4 + kLane;
        const uint32_t vBase = sb + (4608 + (jb % 3) * ASTG + 2304) * 4 + vLane;

        // S = Q K^T  (base-2 logits)
        float s[8][4];
#pragma unroll
        for (int nt = 0; nt < 8; nt++)
#pragma unroll
            for (int f = 0; f < 4; f++) s[nt][f] = 0.f;
#pragma unroll
        for (int ks = 0; ks < 4; ks++) {
            unsigned bf[4][4];
#pragma unroll
            for (int np = 0; np < 4; np++)
                ldsm4(bf[np][0], bf[np][1], bf[np][2], bf[np][3],
                      kBase + np * (16 * 36 * 4) + ks * 32);
#pragma unroll
            for (int np = 0; np < 4; np++) {
                mma16(s[2 * np + 0], qa[ks], &bf[np][0]);
                mma16(s[2 * np + 1], qa[ks], &bf[np][2]);
            }
        }

        // Online softmax (exp2 domain): row max
        float mx0 = -1e30f, mx1 = -1e30f;
#pragma unroll
        for (int nt = 0; nt < 8; nt++) {
            mx0 = fmaxf(mx0, fmaxf(s[nt][0], s[nt][1]));
            mx1 = fmaxf(mx1, fmaxf(s[nt][2], s[nt][3]));
        }
#pragma unroll
        for (int off = 1; off <= 2; off <<= 1) {
            mx0 = fmaxf(mx0, __shfl_xor_sync(0xffffffffu, mx0, off));
            mx1 = fmaxf(mx1, __shfl_xor_sync(0xffffffffu, mx1, off));
        }
        float M0 = fmaxf(m0r, mx0), M1 = fmaxf(m1r, mx1);
        float al0 = fex2(m0r - M0), al1 = fex2(m1r - M1);
        m0r = M0; m1r = M1;

        // P = 2^(S - M) as f16x2; these ARE the PV A-fragment halves.
        unsigned ph[8][2];
#pragma unroll
        for (int nt = 0; nt < 8; nt++) {
            ph[nt][0] = ex2h2(h2(s[nt][0] - M0, s[nt][1] - M0));
            ph[nt][1] = ex2h2(h2(s[nt][2] - M1, s[nt][3] - M1));
        }

        // Rescale O before accumulating this block
#pragma unroll
        for (int nt = 0; nt < 8; nt++) {
            o[nt][0] *= al0; o[nt][1] *= al0;
            o[nt][2] *= al1; o[nt][3] *= al1;
        }

        // O += P V ; row-sums via P @ ones (lsum C-frag: all cols identical)
        float lsum[4] = {0.f, 0.f, 0.f, 0.f};
#pragma unroll
        for (int ks = 0; ks < 4; ks++) {
            unsigned af[4];
            af[0] = ph[2 * ks][0];
            af[1] = ph[2 * ks][1];
            af[2] = ph[2 * ks + 1][0];
            af[3] = ph[2 * ks + 1][1];
            mma16(lsum, af, bones);
#pragma unroll
            for (int np = 0; np < 4; np++) {
                unsigned vf[4];
                ldsm4t(vf[0], vf[1], vf[2], vf[3],
                       vBase + ks * (16 * 36 * 4) + np * 32);
                mma16(o[2 * np + 0], af, &vf[0]);
                mma16(o[2 * np + 1], af, &vf[2]);
            }
        }
        l0 = l0 * al0 + lsum[0];
        l1 = l1 * al1 + lsum[2];
    }

    const int b = bh >> 4, h = bh & 15;
    float inv0 = 1.f / l0, inv1 = 1.f / l1;
    int r0 = q0 + wid * 16 + g, r1 = r0 + 8;
#pragma unroll
    for (int nt = 0; nt < 8; nt++) {
        int c = h * HDI + nt * 8 + 2 * t;
        *(unsigned*)(g_ah + (size_t)(b * TSEQ + r0) * EMBD + c)
            = h2(o[nt][0] * inv0, o[nt][1] * inv0);
        *(unsigned*)(g_ah + (size_t)(b * TSEQ + r1) * EMBD + c)
            = h2(o[nt][2] * inv1, o[nt][3] * inv1);
    }
}

// ---------------------------------------------------------------------------
extern "C" void kernel_launch(void* const* d_in, const int* in_sizes, int n_in,
                              void* d_out, int out_size)
{
    const float* x  = (const float*)d_in[0];
    const float* Wq = (const float*)d_in[1];
    const float* bq = (const float*)d_in[2];
    const float* Wk = (const float*)d_in[3];
    const float* bk = (const float*)d_in[4];
    const float* Wv = (const float*)d_in[5];
    const float* bv = (const float*)d_in[6];
    const float* Wo = (const float*)d_in[7];
    const float* bo = (const float*)d_in[8];
    float* out = (float*)d_out;

    static int inited = 0;
    if (!inited) {
        cudaFuncSetAttribute(qkv_kernel,  cudaFuncAttributeMaxDynamicSharedMemorySize, GEMM_SMEM);
        cudaFuncSetAttribute(proj_kernel, cudaFuncAttributeMaxDynamicSharedMemorySize, GEMM_SMEM);
        cudaFuncSetAttribute(attn_kernel, cudaFuncAttributeMaxDynamicSharedMemorySize, ATTN_SMEM);
        inited = 1;
    }

    cvt_all<<<dim3(128, 5), 256>>>(x, Wq, Wk, Wv, Wo);

    dim3 gq(M_TOT / 128, EMBD / 128, 3);
    qkv_kernel<<<gq, 256, GEMM_SMEM>>>(bq, bk, bv);

    dim3 ga(TSEQ / 128, NB * NH);
    attn_kernel<<<ga, 256, ATTN_SMEM>>>();

    dim3 go(M_TOT / 128, EMBD / 128);
    proj_kernel<<<go, 256, GEMM_SMEM>>>(bo, out);
}